// round 1
// baseline (speedup 1.0000x reference)
#include <cuda_runtime.h>
#include <math.h>

// Problem constants
#define BB   32
#define NN   1024
#define DD   256
#define HH   256
#define EE   256
#define CC   256
#define KTOP 128
#define TEMP 0.1f
#define EPSV 1e-15f

// Output layout (tuple order: xp, adj_p, s, link, ent, clu, recon, node_x)
#define OFF_XP    0L
#define OFF_ADJP  (OFF_XP   + (long)BB*CC*EE)
#define OFF_S     (OFF_ADJP + (long)BB*CC*CC)
#define OFF_LINK  (OFF_S    + (long)BB*NN*CC)
#define OFF_ENT   (OFF_LINK + 1)
#define OFF_CLU   (OFF_ENT  + 1)
#define OFF_RECON (OFF_CLU  + 1)
#define OFF_NX    (OFF_RECON+ 1)

// -------- device scratch (static, allowed) --------
__device__ float  g_deg[BB*NN];
__device__ float  g_agg[(long)BB*NN*DD];
__device__ float  g_buf[(long)BB*NN*HH];
__device__ float  g_sTa[(long)BB*CC*NN];
__device__ float  g_sts[(long)BB*CC*CC];
__device__ float  g_T  [(long)BB*NN*CC];
__device__ float  g_scores[BB*CC];
__device__ float  g_gate[BB*CC];
__device__ double g_acc[4];   // 0=link(ss), 1=recon(ss), 2=ent, 3=clu

__global__ void zero_acc_kernel() {
    if (threadIdx.x < 4) g_acc[threadIdx.x] = 0.0;
}

// -------- degree: deg[row] = max(sum_m adj[row,m], 1) --------
__global__ void deg_kernel(const float* __restrict__ adj) {
    int row  = blockIdx.x * 8 + (threadIdx.x >> 5);
    int lane = threadIdx.x & 31;
    const float* a = adj + (size_t)row * NN;
    float s = 0.f;
    for (int i = lane; i < NN; i += 32) s += a[i];
    #pragma unroll
    for (int o = 16; o; o >>= 1) s += __shfl_xor_sync(0xffffffffu, s, o);
    if (!lane) g_deg[row] = fmaxf(s, 1.f);
}

// -------- generic batched tiled GEMM (64x64x16, 4x4/thread) --------
// TA: 0 => A is [M,K] row-major; 1 => A is [K,M] row-major (A^T logically)
// TB: 0 => B is [K,N] row-major; 1 => B is [N,K] row-major (B^T logically)
// EPI: 0 store, 1 accumulate into C, 2 row-scale by 1/deg, 3 add bias[col]
template<int TA, int TB, int EPI>
__global__ void gemm64(const float* __restrict__ A, const float* __restrict__ Bm,
                       float* __restrict__ Cm,
                       int M, int N, int K,
                       size_t sA, size_t sB, size_t sC,
                       const float* __restrict__ bias,
                       const float* __restrict__ rs, size_t sRS)
{
    const int BM = 64, BN = 64, BK = 16;
    __shared__ float As[16][65];
    __shared__ float Bs[16][65];
    int b = blockIdx.z;
    A  += (size_t)b * sA;
    Bm += (size_t)b * sB;
    Cm += (size_t)b * sC;
    int m0 = blockIdx.y * BM, n0 = blockIdx.x * BN;
    int tid = threadIdx.x;
    int tx = tid & 15, ty = tid >> 4;
    float acc[4][4] = {};
    for (int k0 = 0; k0 < K; k0 += BK) {
        #pragma unroll
        for (int r = 0; r < 4; r++) {
            int lin = tid + r * 256;
            if (TA == 0) { int kl = lin & 15, ml = lin >> 4;
                As[kl][ml] = A[(size_t)(m0 + ml) * K + k0 + kl];
            } else {       int ml = lin & 63, kl = lin >> 6;
                As[kl][ml] = A[(size_t)(k0 + kl) * M + m0 + ml];
            }
        }
        #pragma unroll
        for (int r = 0; r < 4; r++) {
            int lin = tid + r * 256;
            if (TB == 0) { int nl = lin & 63, kl = lin >> 6;
                Bs[kl][nl] = Bm[(size_t)(k0 + kl) * N + n0 + nl];
            } else {       int kl = lin & 15, nl = lin >> 4;
                Bs[kl][nl] = Bm[(size_t)(n0 + nl) * K + k0 + kl];
            }
        }
        __syncthreads();
        #pragma unroll
        for (int k = 0; k < BK; k++) {
            float a[4], bv[4];
            #pragma unroll
            for (int i = 0; i < 4; i++) a[i]  = As[k][ty * 4 + i];
            #pragma unroll
            for (int j = 0; j < 4; j++) bv[j] = Bs[k][tx * 4 + j];
            #pragma unroll
            for (int i = 0; i < 4; i++)
                #pragma unroll
                for (int j = 0; j < 4; j++)
                    acc[i][j] = fmaf(a[i], bv[j], acc[i][j]);
        }
        __syncthreads();
    }
    #pragma unroll
    for (int i = 0; i < 4; i++) {
        int m = m0 + ty * 4 + i;
        float scale = 1.f;
        if (EPI == 2) scale = 1.f / rs[b * sRS + m];
        #pragma unroll
        for (int j = 0; j < 4; j++) {
            int n = n0 + tx * 4 + j;
            float v = acc[i][j];
            if (EPI == 1) v += Cm[(size_t)m * N + n];
            if (EPI == 2) v *= scale;
            if (EPI == 3) v += bias[n];
            Cm[(size_t)m * N + n] = v;
        }
    }
}

// -------- per-row: v = buf+bias ; l2norm ; relu --------
__global__ void norm_relu_kernel(float* __restrict__ buf, const float* __restrict__ bias) {
    int row = blockIdx.x;                 // B*NN rows, HH cols
    float v = buf[(size_t)row * HH + threadIdx.x] + bias[threadIdx.x];
    float ss = v * v;
    #pragma unroll
    for (int o = 16; o; o >>= 1) ss += __shfl_xor_sync(0xffffffffu, ss, o);
    __shared__ float ws[8];
    if ((threadIdx.x & 31) == 0) ws[threadIdx.x >> 5] = ss;
    __syncthreads();
    __shared__ float nrm;
    if (threadIdx.x == 0) {
        float t = 0.f;
        #pragma unroll
        for (int i = 0; i < 8; i++) t += ws[i];
        nrm = fmaxf(sqrtf(t), 1e-12f);
    }
    __syncthreads();
    buf[(size_t)row * HH + threadIdx.x] = fmaxf(v / nrm, 0.f);
}

// -------- row softmax (C=256 cols), in place --------
__global__ void softmax_kernel(float* __restrict__ s) {
    int row = blockIdx.x;
    float v = s[(size_t)row * CC + threadIdx.x];
    float m = v;
    #pragma unroll
    for (int o = 16; o; o >>= 1) m = fmaxf(m, __shfl_xor_sync(0xffffffffu, m, o));
    __shared__ float wm[8];
    if ((threadIdx.x & 31) == 0) wm[threadIdx.x >> 5] = m;
    __syncthreads();
    __shared__ float rowmax;
    if (threadIdx.x == 0) {
        float t = wm[0];
        #pragma unroll
        for (int i = 1; i < 8; i++) t = fmaxf(t, wm[i]);
        rowmax = t;
    }
    __syncthreads();
    float e = expf(v - rowmax);
    float ss = e;
    #pragma unroll
    for (int o = 16; o; o >>= 1) ss += __shfl_xor_sync(0xffffffffu, ss, o);
    __shared__ float wsum[8];
    if ((threadIdx.x & 31) == 0) wsum[threadIdx.x >> 5] = ss;
    __syncthreads();
    __shared__ float rowsum;
    if (threadIdx.x == 0) {
        float t = 0.f;
        #pragma unroll
        for (int i = 0; i < 8; i++) t += wsum[i];
        rowsum = t;
    }
    __syncthreads();
    s[(size_t)row * CC + threadIdx.x] = e / rowsum;
}

// -------- scores[b,c] = sum_n s[b,n,c] --------
__global__ void scores_kernel(const float* __restrict__ s) {
    int idx = blockIdx.x * blockDim.x + threadIdx.x;   // B*C threads
    int b = idx / CC, c = idx % CC;
    const float* p = s + (size_t)b * NN * CC + c;
    float sum = 0.f;
    for (int n = 0; n < NN; n++) sum += p[(size_t)n * CC];
    g_scores[idx] = sum;
}

// -------- per-batch: bitonic sort 256 scores desc, gate = sigmoid((score-thr)/T) --------
__global__ void gate_kernel() {
    __shared__ float v[CC];
    int b = blockIdx.x;
    int i = threadIdx.x;
    v[i] = g_scores[b * CC + i];
    __syncthreads();
    for (int ksz = 2; ksz <= CC; ksz <<= 1) {
        for (int j = ksz >> 1; j > 0; j >>= 1) {
            int ixj = i ^ j;
            if (ixj > i) {
                bool up = ((i & ksz) == 0);      // descending overall
                float a = v[i], bb2 = v[ixj];
                if (up ? (a < bb2) : (a > bb2)) { v[i] = bb2; v[ixj] = a; }
            }
            __syncthreads();
        }
    }
    float thr = v[KTOP - 1];
    float sc  = g_scores[b * CC + i];
    g_gate[b * CC + i] = 1.f / (1.f + expf(-(sc - thr) / TEMP));
}

// -------- s *= gate ; entropy accumulate --------
__global__ void apply_gate_ent_kernel(float* __restrict__ s) {
    int row = blockIdx.x;              // b*NN + n
    int b = row / NN;
    size_t idx = (size_t)row * CC + threadIdx.x;
    float val = s[idx] * g_gate[b * CC + threadIdx.x];
    s[idx] = val;
    float e = -val * logf(val + EPSV);
    #pragma unroll
    for (int o = 16; o; o >>= 1) e += __shfl_xor_sync(0xffffffffu, e, o);
    __shared__ float ws[8];
    if ((threadIdx.x & 31) == 0) ws[threadIdx.x >> 5] = e;
    __syncthreads();
    if (threadIdx.x == 0) {
        float t = 0.f;
        #pragma unroll
        for (int i = 0; i < 8; i++) t += ws[i];
        atomicAdd(&g_acc[2], (double)t);
    }
}

// -------- per-batch cluster (orthogonality) loss from sts --------
__global__ void clu_kernel() {
    int b = blockIdx.x;
    const float* p = g_sts + (size_t)b * CC * CC;
    __shared__ float red[256];
    float ss = 0.f;
    for (int i = threadIdx.x; i < CC * CC; i += 256) { float v = p[i]; ss += v * v; }
    red[threadIdx.x] = ss; __syncthreads();
    for (int o = 128; o; o >>= 1) { if (threadIdx.x < o) red[threadIdx.x] += red[threadIdx.x + o]; __syncthreads(); }
    __shared__ float fro;
    if (threadIdx.x == 0) fro = fmaxf(sqrtf(red[0]), 1e-12f);
    __syncthreads();
    const float inv_sqrtC = rsqrtf((float)CC);
    float ds = 0.f;
    for (int i = threadIdx.x; i < CC * CC; i += 256) {
        int r = i / CC, c = i % CC;
        float d = p[i] / fro - (r == c ? inv_sqrtC : 0.f);
        ds += d * d;
    }
    red[threadIdx.x] = ds; __syncthreads();
    for (int o = 128; o; o >>= 1) { if (threadIdx.x < o) red[threadIdx.x] += red[threadIdx.x + o]; __syncthreads(); }
    if (threadIdx.x == 0) atomicAdd(&g_acc[3], (double)sqrtf(red[0]));
}

// -------- fused link/recon loss: per 64x64 tile compute (ssT) and (T sT), diff vs A --------
__global__ void loss_kernel(const float* __restrict__ adj,
                            const float* __restrict__ s)
{
    const int BK = 16;
    __shared__ float Ss[16][65];  // s rows for n-tile  [k][m]
    __shared__ float Ts[16][65];  // T rows for n-tile  [k][m]
    __shared__ float Sm[16][65];  // s rows for m-tile  [k][n]
    int b  = blockIdx.z;
    const float* sb = s   + (size_t)b * NN * CC;
    const float* Tb = g_T + (size_t)b * NN * CC;
    const float* Ab = adj + (size_t)b * NN * NN;
    int n0 = blockIdx.y * 64;   // row tile
    int m0 = blockIdx.x * 64;   // col tile
    int tid = threadIdx.x;
    int tx = tid & 15, ty = tid >> 4;
    float accP[4][4] = {}, accR[4][4] = {};
    for (int k0 = 0; k0 < CC; k0 += BK) {
        #pragma unroll
        for (int r = 0; r < 4; r++) {
            int lin = tid + r * 256;
            int kl = lin & 15, ml = lin >> 4;
            Ss[kl][ml] = sb[(size_t)(n0 + ml) * CC + k0 + kl];
            Ts[kl][ml] = Tb[(size_t)(n0 + ml) * CC + k0 + kl];
            Sm[kl][ml] = sb[(size_t)(m0 + ml) * CC + k0 + kl];
        }
        __syncthreads();
        #pragma unroll
        for (int k = 0; k < BK; k++) {
            float a[4], t[4], bv[4];
            #pragma unroll
            for (int i = 0; i < 4; i++) { a[i] = Ss[k][ty * 4 + i]; t[i] = Ts[k][ty * 4 + i]; }
            #pragma unroll
            for (int j = 0; j < 4; j++) bv[j] = Sm[k][tx * 4 + j];
            #pragma unroll
            for (int i = 0; i < 4; i++)
                #pragma unroll
                for (int j = 0; j < 4; j++) {
                    accP[i][j] = fmaf(a[i], bv[j], accP[i][j]);
                    accR[i][j] = fmaf(t[i], bv[j], accR[i][j]);
                }
        }
        __syncthreads();
    }
    float sumP = 0.f, sumR = 0.f;
    #pragma unroll
    for (int i = 0; i < 4; i++) {
        int n = n0 + ty * 4 + i;
        #pragma unroll
        for (int j = 0; j < 4; j++) {
            int m = m0 + tx * 4 + j;
            float av = Ab[(size_t)n * NN + m];
            float dp = av - accP[i][j];
            float dr = av - accR[i][j];
            sumP += dp * dp;
            sumR += dr * dr;
        }
    }
    #pragma unroll
    for (int o = 16; o; o >>= 1) {
        sumP += __shfl_xor_sync(0xffffffffu, sumP, o);
        sumR += __shfl_xor_sync(0xffffffffu, sumR, o);
    }
    __shared__ float wp[8], wr[8];
    if ((tid & 31) == 0) { wp[tid >> 5] = sumP; wr[tid >> 5] = sumR; }
    __syncthreads();
    if (tid == 0) {
        float tp = 0.f, tr = 0.f;
        #pragma unroll
        for (int i = 0; i < 8; i++) { tp += wp[i]; tr += wr[i]; }
        atomicAdd(&g_acc[0], (double)tp);
        atomicAdd(&g_acc[1], (double)tr);
    }
}

__global__ void finalize_kernel(float* __restrict__ out) {
    const double numel = (double)BB * NN * NN;
    out[OFF_LINK]  = (float)(sqrt(g_acc[0]) / numel);
    out[OFF_ENT]   = (float)(g_acc[2] / ((double)BB * NN));
    out[OFF_CLU]   = (float)(g_acc[3] / (double)BB);
    out[OFF_RECON] = (float)(sqrt(g_acc[1]) / numel);
}

extern "C" void kernel_launch(void* const* d_in, const int* in_sizes, int n_in,
                              void* d_out, int out_size)
{
    const float* x    = (const float*)d_in[0];
    const float* adj  = (const float*)d_in[1];
    const float* Wr_p = (const float*)d_in[2];
    const float* br_p = (const float*)d_in[3];
    const float* Wo_p = (const float*)d_in[4];
    const float* Wl_p = (const float*)d_in[5];
    const float* bl_p = (const float*)d_in[6];
    const float* Wr_e = (const float*)d_in[7];
    const float* br_e = (const float*)d_in[8];
    const float* Wo_e = (const float*)d_in[9];
    const float* Wl_e = (const float*)d_in[10];
    const float* bl_e = (const float*)d_in[11];

    float* out = (float*)d_out;
    float* S   = out + OFF_S;     // [B,N,C]
    float* NX  = out + OFF_NX;    // [B,N,E]
    float* XP  = out + OFF_XP;    // [B,C,E]
    float* AP  = out + OFF_ADJP;  // [B,C,C]

    float* aggp; cudaGetSymbolAddress((void**)&aggp, g_agg);
    float* bufp; cudaGetSymbolAddress((void**)&bufp, g_buf);
    float* sTap; cudaGetSymbolAddress((void**)&sTap, g_sTa);
    float* stsp; cudaGetSymbolAddress((void**)&stsp, g_sts);
    float* Tp;   cudaGetSymbolAddress((void**)&Tp,   g_T);
    float* degp; cudaGetSymbolAddress((void**)&degp, g_deg);

    zero_acc_kernel<<<1, 32>>>();
    deg_kernel<<<BB * NN / 8, 256>>>(adj);

    // agg = (adj @ x) / deg
    gemm64<0,0,2><<<dim3(DD/64, NN/64, BB), 256>>>(
        adj, x, aggp, NN, DD, NN,
        (size_t)NN*NN, (size_t)NN*DD, (size_t)NN*DD, nullptr, degp, NN);

    // --- pool branch ---
    gemm64<0,0,0><<<dim3(HH/64, NN/64, BB), 256>>>(
        aggp, Wr_p, bufp, NN, HH, DD,
        (size_t)NN*DD, 0, (size_t)NN*HH, nullptr, nullptr, 0);
    gemm64<0,0,1><<<dim3(HH/64, NN/64, BB), 256>>>(
        x, Wo_p, bufp, NN, HH, DD,
        (size_t)NN*DD, 0, (size_t)NN*HH, nullptr, nullptr, 0);
    norm_relu_kernel<<<BB * NN, HH>>>(bufp, br_p);
    gemm64<0,0,3><<<dim3(CC/64, NN/64, BB), 256>>>(
        bufp, Wl_p, S, NN, CC, HH,
        (size_t)NN*HH, 0, (size_t)NN*CC, bl_p, nullptr, 0);

    // --- embed branch ---
    gemm64<0,0,0><<<dim3(HH/64, NN/64, BB), 256>>>(
        aggp, Wr_e, bufp, NN, HH, DD,
        (size_t)NN*DD, 0, (size_t)NN*HH, nullptr, nullptr, 0);
    gemm64<0,0,1><<<dim3(HH/64, NN/64, BB), 256>>>(
        x, Wo_e, bufp, NN, HH, DD,
        (size_t)NN*DD, 0, (size_t)NN*HH, nullptr, nullptr, 0);
    norm_relu_kernel<<<BB * NN, HH>>>(bufp, br_e);
    gemm64<0,0,3><<<dim3(EE/64, NN/64, BB), 256>>>(
        bufp, Wl_e, NX, NN, EE, HH,
        (size_t)NN*HH, 0, (size_t)NN*EE, bl_e, nullptr, 0);

    // softmax + soft-topk gate + entropy
    softmax_kernel<<<BB * NN, CC>>>(S);
    scores_kernel<<<BB * CC / 256, 256>>>(S);
    gate_kernel<<<BB, CC>>>();
    apply_gate_ent_kernel<<<BB * NN, CC>>>(S);

    // xp = s^T @ node_x
    gemm64<1,0,0><<<dim3(EE/64, CC/64, BB), 256>>>(
        S, NX, XP, CC, EE, NN,
        (size_t)NN*CC, (size_t)NN*EE, (size_t)CC*EE, nullptr, nullptr, 0);

    // sTa = s^T @ adj
    gemm64<1,0,0><<<dim3(NN/64, CC/64, BB), 256>>>(
        S, adj, sTap, CC, NN, NN,
        (size_t)NN*CC, (size_t)NN*NN, (size_t)CC*NN, nullptr, nullptr, 0);

    // adj_p = sTa @ s
    gemm64<0,0,0><<<dim3(CC/64, CC/64, BB), 256>>>(
        sTap, S, AP, CC, CC, NN,
        (size_t)CC*NN, (size_t)NN*CC, (size_t)CC*CC, nullptr, nullptr, 0);

    // sts = s^T @ s  -> cluster loss
    gemm64<1,0,0><<<dim3(CC/64, CC/64, BB), 256>>>(
        S, S, stsp, CC, CC, NN,
        (size_t)NN*CC, (size_t)NN*CC, (size_t)CC*CC, nullptr, nullptr, 0);
    clu_kernel<<<BB, 256>>>();

    // T = s @ adj_p
    gemm64<0,0,0><<<dim3(CC/64, NN/64, BB), 256>>>(
        S, AP, Tp, NN, CC, CC,
        (size_t)NN*CC, (size_t)CC*CC, (size_t)NN*CC, nullptr, nullptr, 0);

    // fused link + recon loss over N x N tiles
    loss_kernel<<<dim3(NN/64, NN/64, BB), 256>>>(adj, S);

    finalize_kernel<<<1, 1>>>(out);
    (void)in_sizes; (void)n_in; (void)out_size;
}

// round 2
// speedup vs baseline: 1.6198x; 1.6198x over previous
#include <cuda_runtime.h>
#include <math.h>

// Problem constants
#define BB   32
#define NN   1024
#define DD   256
#define HH   256
#define EE   256
#define CC   256
#define KTOP 128
#define TEMP 0.1f
#define EPSV 1e-15f

// Output layout (tuple order: xp, adj_p, s, link, ent, clu, recon, node_x)
#define OFF_XP    0L
#define OFF_ADJP  (OFF_XP   + (long)BB*CC*EE)
#define OFF_S     (OFF_ADJP + (long)BB*CC*CC)
#define OFF_LINK  (OFF_S    + (long)BB*NN*CC)
#define OFF_ENT   (OFF_LINK + 1)
#define OFF_CLU   (OFF_ENT  + 1)
#define OFF_RECON (OFF_CLU  + 1)
#define OFF_NX    (OFF_RECON+ 1)

// -------- device scratch --------
__device__ float  g_deg[BB*NN];
__device__ float  g_agg[(long)BB*NN*DD];
__device__ float  g_buf[(long)BB*NN*HH];
__device__ float  g_sTa[(long)BB*CC*NN];
__device__ float  g_sts[(long)BB*CC*CC];
__device__ float  g_U  [2L*BB*CC*CC];
__device__ float  g_scores[BB*CC];
__device__ float  g_gate[BB*CC];
// 0=||A||^2, 1=tr(adj_p), 2=ent, 3=clu, 4=||sts||^2, 5=||adj_p||^2, 6=<PG,GP>
__device__ double g_acc[7];

__global__ void zero_acc_kernel() {
    if (threadIdx.x < 7) g_acc[threadIdx.x] = 0.0;
}

// -------- degree + ||A||^2 --------
__global__ void deg_kernel(const float* __restrict__ adj) {
    int row  = blockIdx.x * 8 + (threadIdx.x >> 5);
    int lane = threadIdx.x & 31;
    const float* a = adj + (size_t)row * NN;
    float s = 0.f, sq = 0.f;
    for (int i = lane; i < NN; i += 32) { float v = a[i]; s += v; sq += v * v; }
    #pragma unroll
    for (int o = 16; o; o >>= 1) {
        s  += __shfl_xor_sync(0xffffffffu, s,  o);
        sq += __shfl_xor_sync(0xffffffffu, sq, o);
    }
    __shared__ float wsq[8];
    if (!lane) { g_deg[row] = fmaxf(s, 1.f); wsq[threadIdx.x >> 5] = sq; }
    __syncthreads();
    if (threadIdx.x == 0) {
        float t = 0.f;
        #pragma unroll
        for (int i = 0; i < 8; i++) t += wsq[i];
        atomicAdd(&g_acc[0], (double)t);
    }
}

// -------- batched 128x128x16 GEMM, 8x8/thread, vectorized --------
// TA: 0 => A is [M,K] row-major; 1 => A is [K,M] row-major (logical A^T)
// DUAL: 1 => C = A1@B1 + A2@B2 (both TA=0 semantics use template TA)
// EPI: 0 store, 2 row-scale by 1/rs[b*M+m], 3 add bias[col]
template<int TA, int DUAL, int EPI>
__global__ void __launch_bounds__(256)
gemm128(const float* __restrict__ A1, const float* __restrict__ B1,
        const float* __restrict__ A2, const float* __restrict__ B2,
        float* __restrict__ Cm,
        int M, int N, int K,
        long sA, long sB, long sC,
        const float* __restrict__ bias,
        const float* __restrict__ rs)
{
    __shared__ float As[16][132];
    __shared__ float Bs[16][132];
    const int b = blockIdx.z;
    const float* A1b = A1 + (long)b * sA;
    const float* A2b = DUAL ? (A2 + (long)b * sA) : A1b;
    const float* B1b = B1 + (long)b * sB;
    const float* B2b = DUAL ? (B2 + (long)b * sB) : B1b;
    float* Cb = Cm + (long)b * sC;

    const int m0 = blockIdx.y * 128, n0 = blockIdx.x * 128;
    const int tid = threadIdx.x;
    const int tx = tid & 15, ty = tid >> 4;

    const int TP = K / 16;
    const int T  = DUAL ? 2 * TP : TP;

    float acc[2][4][2][4] = {};
    float4 ra[2], rb[2];

    // ---- initial load (t = 0) ----
    {
        const float* A = A1b; const float* B = B1b; int k0 = 0;
        #pragma unroll
        for (int r = 0; r < 2; r++) {
            int lin = tid + r * 256;
            if (TA == 0) { int ml = lin >> 2, kg = lin & 3;
                ra[r] = *(const float4*)&A[(long)(m0 + ml) * K + k0 + kg * 4];
            } else {       int mg = lin & 31, kl = lin >> 5;
                ra[r] = *(const float4*)&A[(long)(k0 + kl) * M + m0 + mg * 4];
            }
            { int ng = lin & 31, kl = lin >> 5;
                rb[r] = *(const float4*)&B[(long)(k0 + kl) * N + n0 + ng * 4]; }
        }
    }

    for (int t = 0; t < T; t++) {
        // store prefetched tile to smem
        #pragma unroll
        for (int r = 0; r < 2; r++) {
            int lin = tid + r * 256;
            if (TA == 0) { int ml = lin >> 2, kg = lin & 3;
                As[kg * 4 + 0][ml] = ra[r].x;
                As[kg * 4 + 1][ml] = ra[r].y;
                As[kg * 4 + 2][ml] = ra[r].z;
                As[kg * 4 + 3][ml] = ra[r].w;
            } else {       int mg = lin & 31, kl = lin >> 5;
                *(float4*)&As[kl][mg * 4] = ra[r]; }
            { int ng = lin & 31, kl = lin >> 5;
                *(float4*)&Bs[kl][ng * 4] = rb[r]; }
        }
        __syncthreads();

        // prefetch next tile into registers
        if (t + 1 < T) {
            int tn = t + 1;
            int pair = (DUAL && tn >= TP) ? 1 : 0;
            const float* A = pair ? A2b : A1b;
            const float* B = pair ? B2b : B1b;
            int k0 = (pair ? tn - TP : tn) * 16;
            #pragma unroll
            for (int r = 0; r < 2; r++) {
                int lin = tid + r * 256;
                if (TA == 0) { int ml = lin >> 2, kg = lin & 3;
                    ra[r] = *(const float4*)&A[(long)(m0 + ml) * K + k0 + kg * 4];
                } else {       int mg = lin & 31, kl = lin >> 5;
                    ra[r] = *(const float4*)&A[(long)(k0 + kl) * M + m0 + mg * 4];
                }
                { int ng = lin & 31, kl = lin >> 5;
                    rb[r] = *(const float4*)&B[(long)(k0 + kl) * N + n0 + ng * 4]; }
            }
        }

        // compute
        #pragma unroll
        for (int k = 0; k < 16; k++) {
            float4 a0 = *(const float4*)&As[k][ty * 4];
            float4 a1 = *(const float4*)&As[k][64 + ty * 4];
            float4 b0 = *(const float4*)&Bs[k][tx * 4];
            float4 b1 = *(const float4*)&Bs[k][64 + tx * 4];
            float av[2][4] = {{a0.x, a0.y, a0.z, a0.w}, {a1.x, a1.y, a1.z, a1.w}};
            float bv[2][4] = {{b0.x, b0.y, b0.z, b0.w}, {b1.x, b1.y, b1.z, b1.w}};
            #pragma unroll
            for (int ih = 0; ih < 2; ih++)
                #pragma unroll
                for (int i = 0; i < 4; i++)
                    #pragma unroll
                    for (int jh = 0; jh < 2; jh++)
                        #pragma unroll
                        for (int j = 0; j < 4; j++)
                            acc[ih][i][jh][j] = fmaf(av[ih][i], bv[jh][j], acc[ih][i][jh][j]);
        }
        __syncthreads();
    }

    // epilogue (float4 stores)
    #pragma unroll
    for (int ih = 0; ih < 2; ih++)
        #pragma unroll
        for (int i = 0; i < 4; i++) {
            int m = m0 + ih * 64 + ty * 4 + i;
            float sc = 1.f;
            if (EPI == 2) sc = 1.f / rs[(long)b * M + m];
            #pragma unroll
            for (int jh = 0; jh < 2; jh++) {
                int n = n0 + jh * 64 + tx * 4;
                float4 v;
                v.x = acc[ih][i][jh][0]; v.y = acc[ih][i][jh][1];
                v.z = acc[ih][i][jh][2]; v.w = acc[ih][i][jh][3];
                if (EPI == 2) { v.x *= sc; v.y *= sc; v.z *= sc; v.w *= sc; }
                if (EPI == 3) {
                    v.x += bias[n]; v.y += bias[n + 1];
                    v.z += bias[n + 2]; v.w += bias[n + 3];
                }
                *(float4*)&Cb[(long)m * N + n] = v;
            }
        }
}

// -------- per-row: v = buf+bias ; l2norm ; relu --------
__global__ void norm_relu_kernel(float* __restrict__ buf, const float* __restrict__ bias) {
    int row = blockIdx.x;
    float v = buf[(size_t)row * HH + threadIdx.x] + bias[threadIdx.x];
    float ss = v * v;
    #pragma unroll
    for (int o = 16; o; o >>= 1) ss += __shfl_xor_sync(0xffffffffu, ss, o);
    __shared__ float ws[8];
    if ((threadIdx.x & 31) == 0) ws[threadIdx.x >> 5] = ss;
    __syncthreads();
    __shared__ float nrm;
    if (threadIdx.x == 0) {
        float t = 0.f;
        #pragma unroll
        for (int i = 0; i < 8; i++) t += ws[i];
        nrm = fmaxf(sqrtf(t), 1e-12f);
    }
    __syncthreads();
    buf[(size_t)row * HH + threadIdx.x] = fmaxf(v / nrm, 0.f);
}

// -------- row softmax --------
__global__ void softmax_kernel(float* __restrict__ s) {
    int row = blockIdx.x;
    float v = s[(size_t)row * CC + threadIdx.x];
    float m = v;
    #pragma unroll
    for (int o = 16; o; o >>= 1) m = fmaxf(m, __shfl_xor_sync(0xffffffffu, m, o));
    __shared__ float wm[8];
    if ((threadIdx.x & 31) == 0) wm[threadIdx.x >> 5] = m;
    __syncthreads();
    __shared__ float rowmax;
    if (threadIdx.x == 0) {
        float t = wm[0];
        #pragma unroll
        for (int i = 1; i < 8; i++) t = fmaxf(t, wm[i]);
        rowmax = t;
    }
    __syncthreads();
    float e = expf(v - rowmax);
    float ss = e;
    #pragma unroll
    for (int o = 16; o; o >>= 1) ss += __shfl_xor_sync(0xffffffffu, ss, o);
    __shared__ float wsum[8];
    if ((threadIdx.x & 31) == 0) wsum[threadIdx.x >> 5] = ss;
    __syncthreads();
    __shared__ float rowsum;
    if (threadIdx.x == 0) {
        float t = 0.f;
        #pragma unroll
        for (int i = 0; i < 8; i++) t += wsum[i];
        rowsum = t;
    }
    __syncthreads();
    s[(size_t)row * CC + threadIdx.x] = e / rowsum;
}

// -------- scores[b,c] = sum_n s[b,n,c] --------
__global__ void scores_kernel(const float* __restrict__ s) {
    int idx = blockIdx.x * blockDim.x + threadIdx.x;
    int b = idx / CC, c = idx % CC;
    const float* p = s + (size_t)b * NN * CC + c;
    float sum = 0.f;
    for (int n = 0; n < NN; n++) sum += p[(size_t)n * CC];
    g_scores[idx] = sum;
}

// -------- per-batch bitonic sort, gate --------
__global__ void gate_kernel() {
    __shared__ float v[CC];
    int b = blockIdx.x;
    int i = threadIdx.x;
    v[i] = g_scores[b * CC + i];
    __syncthreads();
    for (int ksz = 2; ksz <= CC; ksz <<= 1) {
        for (int j = ksz >> 1; j > 0; j >>= 1) {
            int ixj = i ^ j;
            if (ixj > i) {
                bool up = ((i & ksz) == 0);
                float a = v[i], bb2 = v[ixj];
                if (up ? (a < bb2) : (a > bb2)) { v[i] = bb2; v[ixj] = a; }
            }
            __syncthreads();
        }
    }
    float thr = v[KTOP - 1];
    float sc  = g_scores[b * CC + i];
    g_gate[b * CC + i] = 1.f / (1.f + expf(-(sc - thr) / TEMP));
}

// -------- s *= gate ; entropy --------
__global__ void apply_gate_ent_kernel(float* __restrict__ s) {
    int row = blockIdx.x;
    int b = row / NN;
    size_t idx = (size_t)row * CC + threadIdx.x;
    float val = s[idx] * g_gate[b * CC + threadIdx.x];
    s[idx] = val;
    float e = -val * logf(val + EPSV);
    #pragma unroll
    for (int o = 16; o; o >>= 1) e += __shfl_xor_sync(0xffffffffu, e, o);
    __shared__ float ws[8];
    if ((threadIdx.x & 31) == 0) ws[threadIdx.x >> 5] = e;
    __syncthreads();
    if (threadIdx.x == 0) {
        float t = 0.f;
        #pragma unroll
        for (int i = 0; i < 8; i++) t += ws[i];
        atomicAdd(&g_acc[2], (double)t);
    }
}

// -------- per-batch cluster loss + ||sts||^2 --------
__global__ void clu_kernel() {
    int b = blockIdx.x;
    const float* p = g_sts + (size_t)b * CC * CC;
    __shared__ float red[256];
    float ss = 0.f;
    for (int i = threadIdx.x; i < CC * CC; i += 256) { float v = p[i]; ss += v * v; }
    red[threadIdx.x] = ss; __syncthreads();
    for (int o = 128; o; o >>= 1) { if (threadIdx.x < o) red[threadIdx.x] += red[threadIdx.x + o]; __syncthreads(); }
    __shared__ float fro;
    if (threadIdx.x == 0) {
        fro = fmaxf(sqrtf(red[0]), 1e-12f);
        atomicAdd(&g_acc[4], (double)red[0]);
    }
    __syncthreads();
    const float inv_sqrtC = rsqrtf((float)CC);
    float ds = 0.f;
    for (int i = threadIdx.x; i < CC * CC; i += 256) {
        int r = i / CC, c = i % CC;
        float d = p[i] / fro - (r == c ? inv_sqrtC : 0.f);
        ds += d * d;
    }
    red[threadIdx.x] = ds; __syncthreads();
    for (int o = 128; o; o >>= 1) { if (threadIdx.x < o) red[threadIdx.x] += red[threadIdx.x + o]; __syncthreads(); }
    if (threadIdx.x == 0) atomicAdd(&g_acc[3], (double)sqrtf(red[0]));
}

// -------- per-batch ||adj_p||^2 and trace(adj_p) --------
__global__ void ap_stats_kernel(const float* __restrict__ AP) {
    int b = blockIdx.x;
    const float* p = AP + (size_t)b * CC * CC;
    float ss = 0.f, tr = 0.f;
    for (int i = threadIdx.x; i < CC * CC; i += 256) {
        float v = p[i];
        ss += v * v;
        if (i % (CC + 1) == 0) tr += v;
    }
    __shared__ float r1[256], r2[256];
    r1[threadIdx.x] = ss; r2[threadIdx.x] = tr; __syncthreads();
    for (int o = 128; o; o >>= 1) {
        if (threadIdx.x < o) { r1[threadIdx.x] += r1[threadIdx.x + o]; r2[threadIdx.x] += r2[threadIdx.x + o]; }
        __syncthreads();
    }
    if (threadIdx.x == 0) {
        atomicAdd(&g_acc[5], (double)r1[0]);
        atomicAdd(&g_acc[1], (double)r2[0]);
    }
}

// -------- <U1, U2> --------
__global__ void dot_kernel() {
    const long total = (long)BB * CC * CC;
    const float* U1 = g_U;
    const float* U2 = g_U + total;
    long stride = (long)gridDim.x * blockDim.x;
    float s = 0.f;
    for (long i = blockIdx.x * (long)blockDim.x + threadIdx.x; i < total; i += stride)
        s += U1[i] * U2[i];
    __shared__ float red[256];
    red[threadIdx.x] = s; __syncthreads();
    for (int o = 128; o; o >>= 1) { if (threadIdx.x < o) red[threadIdx.x] += red[threadIdx.x + o]; __syncthreads(); }
    if (threadIdx.x == 0) atomicAdd(&g_acc[6], (double)red[0]);
}

__global__ void finalize_kernel(float* __restrict__ out) {
    const double numel = (double)BB * NN * NN;
    double linkSq  = g_acc[0] - 2.0 * g_acc[1] + g_acc[4];
    double reconSq = g_acc[0] - 2.0 * g_acc[5] + g_acc[6];
    if (linkSq  < 0.0) linkSq  = 0.0;
    if (reconSq < 0.0) reconSq = 0.0;
    out[OFF_LINK]  = (float)(sqrt(linkSq)  / numel);
    out[OFF_ENT]   = (float)(g_acc[2] / ((double)BB * NN));
    out[OFF_CLU]   = (float)(g_acc[3] / (double)BB);
    out[OFF_RECON] = (float)(sqrt(reconSq) / numel);
}

extern "C" void kernel_launch(void* const* d_in, const int* in_sizes, int n_in,
                              void* d_out, int out_size)
{
    const float* x    = (const float*)d_in[0];
    const float* adj  = (const float*)d_in[1];
    const float* Wr_p = (const float*)d_in[2];
    const float* br_p = (const float*)d_in[3];
    const float* Wo_p = (const float*)d_in[4];
    const float* Wl_p = (const float*)d_in[5];
    const float* bl_p = (const float*)d_in[6];
    const float* Wr_e = (const float*)d_in[7];
    const float* br_e = (const float*)d_in[8];
    const float* Wo_e = (const float*)d_in[9];
    const float* Wl_e = (const float*)d_in[10];
    const float* bl_e = (const float*)d_in[11];

    float* out = (float*)d_out;
    float* S   = out + OFF_S;
    float* NX  = out + OFF_NX;
    float* XP  = out + OFF_XP;
    float* AP  = out + OFF_ADJP;

    float* aggp; cudaGetSymbolAddress((void**)&aggp, g_agg);
    float* bufp; cudaGetSymbolAddress((void**)&bufp, g_buf);
    float* sTap; cudaGetSymbolAddress((void**)&sTap, g_sTa);
    float* stsp; cudaGetSymbolAddress((void**)&stsp, g_sts);
    float* Up;   cudaGetSymbolAddress((void**)&Up,   g_U);
    float* degp; cudaGetSymbolAddress((void**)&degp, g_deg);

    zero_acc_kernel<<<1, 32>>>();
    deg_kernel<<<BB * NN / 8, 256>>>(adj);

    // agg = (adj @ x) / deg
    gemm128<0,0,2><<<dim3(DD/128, NN/128, BB), 256>>>(
        adj, x, nullptr, nullptr, aggp, NN, DD, NN,
        (long)NN*NN, (long)NN*DD, (long)NN*DD, nullptr, degp);

    // --- pool branch: buf = agg@Wr_p + x@Wo_p ---
    gemm128<0,1,0><<<dim3(HH/128, NN/128, BB), 256>>>(
        aggp, Wr_p, x, Wo_p, bufp, NN, HH, DD,
        (long)NN*DD, 0L, (long)NN*HH, nullptr, nullptr);
    norm_relu_kernel<<<BB * NN, HH>>>(bufp, br_p);
    gemm128<0,0,3><<<dim3(CC/128, NN/128, BB), 256>>>(
        bufp, Wl_p, nullptr, nullptr, S, NN, CC, HH,
        (long)NN*HH, 0L, (long)NN*CC, bl_p, nullptr);

    // --- embed branch ---
    gemm128<0,1,0><<<dim3(HH/128, NN/128, BB), 256>>>(
        aggp, Wr_e, x, Wo_e, bufp, NN, HH, DD,
        (long)NN*DD, 0L, (long)NN*HH, nullptr, nullptr);
    norm_relu_kernel<<<BB * NN, HH>>>(bufp, br_e);
    gemm128<0,0,3><<<dim3(EE/128, NN/128, BB), 256>>>(
        bufp, Wl_e, nullptr, nullptr, NX, NN, EE, HH,
        (long)NN*HH, 0L, (long)NN*EE, bl_e, nullptr);

    // softmax + soft-topk gate + entropy
    softmax_kernel<<<BB * NN, CC>>>(S);
    scores_kernel<<<BB * CC / 256, 256>>>(S);
    gate_kernel<<<BB, CC>>>();
    apply_gate_ent_kernel<<<BB * NN, CC>>>(S);

    // xp = s^T @ node_x
    gemm128<1,0,0><<<dim3(EE/128, CC/128, BB), 256>>>(
        S, NX, nullptr, nullptr, XP, CC, EE, NN,
        (long)NN*CC, (long)NN*EE, (long)CC*EE, nullptr, nullptr);

    // sTa = s^T @ adj
    gemm128<1,0,0><<<dim3(NN/128, CC/128, BB), 256>>>(
        S, adj, nullptr, nullptr, sTap, CC, NN, NN,
        (long)NN*CC, (long)NN*NN, (long)CC*NN, nullptr, nullptr);

    // adj_p = sTa @ s
    gemm128<0,0,0><<<dim3(CC/128, CC/128, BB), 256>>>(
        sTap, S, nullptr, nullptr, AP, CC, CC, NN,
        (long)CC*NN, (long)NN*CC, (long)CC*CC, nullptr, nullptr);

    // sts = s^T @ s
    gemm128<1,0,0><<<dim3(CC/128, CC/128, BB), 256>>>(
        S, S, nullptr, nullptr, stsp, CC, CC, NN,
        (long)NN*CC, (long)NN*CC, (long)CC*CC, nullptr, nullptr);

    // U1 = AP @ sts ; U2 = sts @ AP
    gemm128<0,0,0><<<dim3(CC/128, CC/128, BB), 256>>>(
        AP, stsp, nullptr, nullptr, Up, CC, CC, CC,
        (long)CC*CC, (long)CC*CC, (long)CC*CC, nullptr, nullptr);
    gemm128<0,0,0><<<dim3(CC/128, CC/128, BB), 256>>>(
        stsp, AP, nullptr, nullptr, Up + (long)BB*CC*CC, CC, CC, CC,
        (long)CC*CC, (long)CC*CC, (long)CC*CC, nullptr, nullptr);

    // reductions
    clu_kernel<<<BB, 256>>>();
    ap_stats_kernel<<<BB, 256>>>(AP);
    dot_kernel<<<128, 256>>>();

    finalize_kernel<<<1, 1>>>(out);
    (void)in_sizes; (void)n_in; (void)out_size;
}